// round 17
// baseline (speedup 1.0000x reference)
#include <cuda_runtime.h>
#include <cstdint>

// SelMaxPool via bin + gather (single-phase, dual-row float4 gather,
// cache-policy hints):
//   pooled[m][c] = max( max_{j<pool} x[m*pool+j][c],
//                       max_{e active, dst[e]/pool == m} x[src[e]][c] )
// bin -> gather -> overflow+zero.
// Streaming (__ldcs/__stcs) on all stream-once data so L2 capacity is
// reserved for x rows (re-read ~3.5x by random gathers) and bin counters.

#define CH 64                 // channels (64 floats = 16 float4 per row)
#define M_MAX 131072          // max clusters supported by static scratch
#define CAP 96                // bin capacity per cluster (E[load] ~= 14)
#define OVF_CAP 262144

__device__ int g_cnt[M_MAX];
__device__ int g_bins[(size_t)M_MAX * CAP];
__device__ int g_ovf_cnt;
__device__ int g_ovf[2 * OVF_CAP];

__device__ __forceinline__ void atomicMaxFloat(float* addr, float val) {
    if (val >= 0.0f) atomicMax((int*)addr, __float_as_int(val));
    else             atomicMin((unsigned int*)addr, __float_as_uint(val));
}

__global__ void bin_edges_kernel(const int* __restrict__ src,
                                 const int* __restrict__ dst,
                                 const int* __restrict__ sel,
                                 const int* __restrict__ ks_ptr,
                                 int E, int pool, int sh) {
    int e = blockIdx.x * blockDim.x + threadIdx.x;
    if (e >= E) return;
    int k = ks_ptr[0];
    if (__ldcs(sel + e) >= k * k) return;      // stream-once reads
    int d = __ldcs(dst + e);
    int c = (sh >= 0) ? (d >> sh) : (d / pool);
    int s = __ldcs(src + e);
    int slot = atomicAdd(&g_cnt[c], 1);
    if (slot < CAP) {
        g_bins[(size_t)c * CAP + slot] = s;
    } else {
        int o = atomicAdd(&g_ovf_cnt, 1);
        if (o < OVF_CAP) { g_ovf[2 * o] = s; g_ovf[2 * o + 1] = c; }
    }
}

__device__ __forceinline__ float4 fmax4(float4 a, float4 b) {
    a.x = fmaxf(a.x, b.x); a.y = fmaxf(a.y, b.y);
    a.z = fmaxf(a.z, b.z); a.w = fmaxf(a.w, b.w);
    return a;
}

// One warp per cluster. half = lane>>4 selects which of 2 concurrent rows
// this lane helps load; hl = lane&15 is the float4 position within the row.
__global__ void __launch_bounds__(256)
gather_max_kernel(const float* __restrict__ x,
                  float* __restrict__ out,
                  int M, int pool) {
    int warp = (blockIdx.x * blockDim.x + threadIdx.x) >> 5;
    int lane = threadIdx.x & 31;
    if (warp >= M) return;
    const unsigned FULL = 0xffffffffu;
    int half = lane >> 4;
    int hl = lane & 15;
    const float4* __restrict__ xr = (const float4*)x;  // 16 float4 per row

    // Own rows, two at a time (row index clamped for small/odd pool;
    // duplicate reads are harmless under max). Default-cached: these pulls
    // are exactly the lines the random gathers re-read.
    size_t obase = (size_t)warp * pool;
    int pl = pool - 1;
    float4 acc = __ldg(&xr[(obase + min(half, pl)) * 16 + hl]);
    for (int j = 2; j < pool; j += 2)
        acc = fmax4(acc, __ldg(&xr[(obase + min(j + half, pl)) * 16 + hl]));

    int cnt = __ldcs(&g_cnt[warp]);            // read-once scratch
    if (cnt > CAP) cnt = CAP;

    if (cnt > 0) {
        size_t bbase = (size_t)warp * CAP;
        int last = cnt - 1;
        // Clamped prefetch: every lane's slot index is valid.
        int b0 = __ldcs(&g_bins[bbase + min(lane, last)]);
        int b1 = (cnt > 32) ? __ldcs(&g_bins[bbase + min(lane + 32, last)]) : 0;
        int b2 = (cnt > 64) ? __ldcs(&g_bins[bbase + min(lane + 64, last)]) : 0;

        int chunks[3]; chunks[0] = b0; chunks[1] = b1; chunks[2] = b2;
        #pragma unroll
        for (int ch = 0; ch < 3; ch++) {
            int n = cnt - ch * 32;
            if (n <= 0) break;
            if (n > 32) n = 32;
            int b = chunks[ch];
            int nl = n - 1;
            int nb = (n + 15) & ~15;        // round up to multiple of 16
            for (int i = 0; i < nb; i += 16) {
                // 8 loads in flight, each covering 2 rows (512B).
                int s0 = __shfl_sync(FULL, b, min(i +      half, nl));
                int s1 = __shfl_sync(FULL, b, min(i + 2  + half, nl));
                int s2 = __shfl_sync(FULL, b, min(i + 4  + half, nl));
                int s3 = __shfl_sync(FULL, b, min(i + 6  + half, nl));
                int s4 = __shfl_sync(FULL, b, min(i + 8  + half, nl));
                int s5 = __shfl_sync(FULL, b, min(i + 10 + half, nl));
                int s6 = __shfl_sync(FULL, b, min(i + 12 + half, nl));
                int s7 = __shfl_sync(FULL, b, min(i + 14 + half, nl));
                float4 v0 = __ldg(&xr[(size_t)s0 * 16 + hl]);
                float4 v1 = __ldg(&xr[(size_t)s1 * 16 + hl]);
                float4 v2 = __ldg(&xr[(size_t)s2 * 16 + hl]);
                float4 v3 = __ldg(&xr[(size_t)s3 * 16 + hl]);
                float4 v4 = __ldg(&xr[(size_t)s4 * 16 + hl]);
                float4 v5 = __ldg(&xr[(size_t)s5 * 16 + hl]);
                float4 v6 = __ldg(&xr[(size_t)s6 * 16 + hl]);
                float4 v7 = __ldg(&xr[(size_t)s7 * 16 + hl]);
                float4 m0 = fmax4(fmax4(v0, v1), fmax4(v2, v3));
                float4 m1 = fmax4(fmax4(v4, v5), fmax4(v6, v7));
                acc = fmax4(acc, fmax4(m0, m1));
            }
        }
    }

    // Merge the two half-warp accumulators (channels identical; rows differ).
    acc.x = fmaxf(acc.x, __shfl_xor_sync(FULL, acc.x, 16));
    acc.y = fmaxf(acc.y, __shfl_xor_sync(FULL, acc.y, 16));
    acc.z = fmaxf(acc.z, __shfl_xor_sync(FULL, acc.z, 16));
    acc.w = fmaxf(acc.w, __shfl_xor_sync(FULL, acc.w, 16));

    if (half == 0)
        __stcs(&((float4*)out)[(size_t)warp * 16 + hl], acc);  // evict-first

    // NOTE: no scratch maintenance / fences here — keep the hot kernel clean.
}

// Cold-path kernel: handles bin overflow (normally empty) AND re-zeroes the
// scratch counters for the next graph replay. Runs AFTER gather inits out.
__global__ void overflow_zero_kernel(const float* __restrict__ x,
                                     float* __restrict__ out, int M) {
    int gtid = blockIdx.x * blockDim.x + threadIdx.x;
    if (gtid < M) g_cnt[gtid] = 0;

    if (blockIdx.x == 0) {
        int n = g_ovf_cnt; if (n > OVF_CAP) n = OVF_CAP;
        int warp = threadIdx.x >> 5;
        int lane = threadIdx.x & 31;
        const float2* xr = (const float2*)x;
        for (int i = warp; i < n; i += blockDim.x / 32) {
            int s = g_ovf[2 * i], c = g_ovf[2 * i + 1];
            float2 v = xr[(size_t)s * (CH / 2) + lane];
            float* o = out + (size_t)c * CH + lane * 2;
            atomicMaxFloat(o, v.x);
            atomicMaxFloat(o + 1, v.y);
        }
        __syncthreads();
        if (threadIdx.x == 0) g_ovf_cnt = 0;
    }
}

// ---- Fallback (M > M_MAX): direct atomic scatter path ----
__global__ void pool_init_kernel(const float* __restrict__ x,
                                 float* __restrict__ out, int total, int pool) {
    int t = blockIdx.x * blockDim.x + threadIdx.x;
    if (t >= total) return;
    int m = t >> 4, cg = t & 15;
    const float4* xr = (const float4*)x + (size_t)m * (pool * (CH / 4)) + cg;
    float4 r = xr[0];
    for (int j = 1; j < pool; j++) {
        float4 a = xr[(size_t)j * (CH / 4)];
        r.x = fmaxf(r.x, a.x); r.y = fmaxf(r.y, a.y);
        r.z = fmaxf(r.z, a.z); r.w = fmaxf(r.w, a.w);
    }
    ((float4*)out)[t] = r;
}

__global__ void edge_scatter_kernel(const float* __restrict__ x,
                                    const int* __restrict__ src,
                                    const int* __restrict__ dst,
                                    const int* __restrict__ sel,
                                    const int* __restrict__ ks_ptr,
                                    float* __restrict__ out,
                                    int E, int pool, int sh) {
    int gwarp = (blockIdx.x * blockDim.x + threadIdx.x) >> 5;
    int lane = threadIdx.x & 31;
    int base = gwarp * 32;
    if (base >= E) return;
    int k = ks_ptr[0]; int thresh = k * k;
    int e = base + lane;
    int s = 0, d = 0; bool act = false;
    if (e < E) { int se = sel[e]; s = src[e]; d = dst[e]; act = (se < thresh); }
    unsigned mask = __ballot_sync(0xffffffffu, act);
    while (mask) {
        int l = __ffs(mask) - 1; mask &= mask - 1;
        int ss = __shfl_sync(0xffffffffu, s, l);
        int dd = __shfl_sync(0xffffffffu, d, l);
        int c = (sh >= 0) ? (dd >> sh) : (dd / pool);
        float2 v = ((const float2*)(x + (size_t)ss * CH))[lane];
        float* o = out + (size_t)c * CH + lane * 2;
        atomicMaxFloat(o, v.x);
        atomicMaxFloat(o + 1, v.y);
    }
}

extern "C" void kernel_launch(void* const* d_in, const int* in_sizes, int n_in,
                              void* d_out, int out_size) {
    const float* x   = (const float*)d_in[0];
    const int*   ei  = (const int*)d_in[1];   // [2,E]: src row then dst row
    const int*   sel = (const int*)d_in[2];
    const int*   ks  = (const int*)d_in[4];
    float* out = (float*)d_out;

    int E = in_sizes[1] / 2;
    int N = in_sizes[3];          // cluster array length
    int M = out_size / CH;
    int pool = N / M;
    int sh = -1;
    for (int b = 0; b < 31; b++) if ((1 << b) == pool) { sh = b; break; }

    const int* src = ei;
    const int* dst = ei + E;

    if (M <= M_MAX) {
        bin_edges_kernel<<<(E + 255) / 256, 256>>>(src, dst, sel, ks, E, pool, sh);
        int threads = M * 32;
        gather_max_kernel<<<(threads + 255) / 256, 256>>>(x, out, M, pool);
        overflow_zero_kernel<<<(M + 255) / 256, 256>>>(x, out, M);
    } else {
        int totalA = M * (CH / 4);
        pool_init_kernel<<<(totalA + 255) / 256, 256>>>(x, out, totalA, pool);
        int warps = (E + 31) / 32;
        int threads = warps * 32;
        edge_scatter_kernel<<<(threads + 255) / 256, 256>>>(
            x, src, dst, sel, ks, out, E, pool, sh);
    }
}